// round 12
// baseline (speedup 1.0000x reference)
#include <cuda_runtime.h>
#include <cstdint>

// Max-unpool scatter, deterministic last-index-wins (matches reference).
//
// Round-12: kill the cross-replay writeback debt.
//   Model (fits R5/R10/R11): the 103MB of dirty `out` lines left by compact
//   drain to DRAM during the NEXT call's Z/S, throttling the latency-bound
//   atomic phase. Fix: compact writes `out` with __stwt (write-through), so
//   the DRAM traffic is paid inside compact's measured bandwidth headroom
//   (DRAM=49.8%) and no dirty-line debt survives the call.
//   Z: block-strided 4x uint4/thread (fast form, now safe: no drain overlap)
//   S: atomicMax(scr[pos[i]], i+1), 8 atomics/thread, pos __ldcs (R5 exact)
//   C: linear 8/thread; scratch __ldcs, x __ldg, out __stwt.

#define N_OUT_CONST 25690112  // 32*112*112*64

__device__ unsigned int g_winner[N_OUT_CONST];

// Each block owns 4*T consecutive uint4 slots; thread t stores slots
// base+t+k*T, k=0..3 (warp-coalesced full 128B lines, ILP=4).
__global__ void zero_scratch_kernel() {
    const int T = blockDim.x;
    int base = blockIdx.x * (T * 4) + threadIdx.x;
    uint4* p = reinterpret_cast<uint4*>(g_winner);
    uint4 z = make_uint4(0u, 0u, 0u, 0u);
    p[base + 0 * T] = z;
    p[base + 1 * T] = z;
    p[base + 2 * T] = z;
    p[base + 3 * T] = z;
}

// n8 = n/8 threads, each loads 2 int4 of pos and issues 8 fire-and-forget
// RED.MAX (measured-best scatter batching).
__global__ void scatter_kernel(const int4* __restrict__ p4, int n8) {
    int t = blockIdx.x * blockDim.x + threadIdx.x;
    if (t >= n8) return;
    int4 a = __ldcs(&p4[2 * t + 0]);
    int4 b = __ldcs(&p4[2 * t + 1]);
    unsigned int base = (unsigned int)(t * 8);
    atomicMax(&g_winner[a.x], base + 1u);
    atomicMax(&g_winner[a.y], base + 2u);
    atomicMax(&g_winner[a.z], base + 3u);
    atomicMax(&g_winner[a.w], base + 4u);
    atomicMax(&g_winner[b.x], base + 5u);
    atomicMax(&g_winner[b.y], base + 6u);
    atomicMax(&g_winner[b.z], base + 7u);
    atomicMax(&g_winner[b.w], base + 8u);
}

// Linear form: thread t consumes uint4 slots 2t, 2t+1 (L1 reuse on the
// second load), 8 gathers batched, 2 float4 WRITE-THROUGH stores (out pays
// its DRAM cost here, leaving no dirty-line debt for the next call).
__global__ void compact_kernel(float* __restrict__ out,
                               const float* __restrict__ x,
                               int count8) {
    int t = blockIdx.x * blockDim.x + threadIdx.x;
    if (t >= count8) return;

    const uint4* __restrict__ sp = reinterpret_cast<const uint4*>(g_winner);
    float4* __restrict__ op = reinterpret_cast<float4*>(out);

    uint4 w0 = __ldcs(&sp[2 * t + 0]);
    uint4 w1 = __ldcs(&sp[2 * t + 1]);

    float4 o0, o1;
    o0.x = w0.x ? __ldg(&x[w0.x - 1u]) : 0.0f;
    o0.y = w0.y ? __ldg(&x[w0.y - 1u]) : 0.0f;
    o0.z = w0.z ? __ldg(&x[w0.z - 1u]) : 0.0f;
    o0.w = w0.w ? __ldg(&x[w0.w - 1u]) : 0.0f;
    o1.x = w1.x ? __ldg(&x[w1.x - 1u]) : 0.0f;
    o1.y = w1.y ? __ldg(&x[w1.y - 1u]) : 0.0f;
    o1.z = w1.z ? __ldg(&x[w1.z - 1u]) : 0.0f;
    o1.w = w1.w ? __ldg(&x[w1.w - 1u]) : 0.0f;

    __stwt(&op[2 * t + 0], o0);
    __stwt(&op[2 * t + 1], o1);
}

extern "C" void kernel_launch(void* const* d_in, const int* in_sizes, int n_in,
                              void* d_out, int out_size) {
    const float* x = reinterpret_cast<const float*>(d_in[0]);
    const int* pos = reinterpret_cast<const int*>(d_in[1]);
    float* out     = reinterpret_cast<float*>(d_out);

    int n = in_sizes[0];             // 6,422,528 (divisible by 8)
    int n8 = n / 8;                  // 802,816
    int count4 = out_size / 4;       // 6,422,528 uint4 slots
    int count8 = out_size / 8;       // 3,211,264

    const int T = 256;
    const int ZG = count4 / (4 * T); // exact: count4 = 6272*1024
    const int SG = (n8 + T - 1) / T;
    const int CG = (count8 + T - 1) / T;

    // Z: zero + L2-heat the winner scratch right before the atomics.
    zero_scratch_kernel<<<ZG, T>>>();

    // S: deterministic last-index-wins via 32-bit atomicMax, 8/thread.
    scatter_kernel<<<SG, T>>>(reinterpret_cast<const int4*>(pos), n8);

    // C: gather winners' values, zero-fill empties, write-through out.
    compact_kernel<<<CG, T>>>(out, x, count8);
}

// round 13
// speedup vs baseline: 1.0013x; 1.0013x over previous
#include <cuda_runtime.h>
#include <cstdint>

// Max-unpool scatter, deterministic last-index-wins (matches reference).
//
// Round-13: SCRATCH ELIMINATED — winner indices resolved inside d_out.
//   out (uint32 view) doubles as the winner-index array; compact converts
//   in-place. Total array footprint drops 258MB -> 155MB (~L2 capacity),
//   so the atomic phase and the compact read side stay L2-resident.
//   Z: zero out, 4x uint4/thread block-strided (coalesced, ILP=4)
//   S: atomicMax((uint*)out + pos[i], i+1), 8 atomics/thread, pos __ldcs
//   C: in-place: w = out[j]; out[j] = w ? x[w-1] : 0  (linear 8/thread)
//   Graph-replay safe: every call re-zeros out; no persistent state.

// Z: each block owns 4*T consecutive uint4 slots; thread t stores slots
// base+t+k*T, k=0..3 (warp-coalesced full 128B lines, ILP=4).
__global__ void zero_out_kernel(unsigned int* __restrict__ outw) {
    const int T = blockDim.x;
    int base = blockIdx.x * (T * 4) + threadIdx.x;
    uint4* p = reinterpret_cast<uint4*>(outw);
    uint4 z = make_uint4(0u, 0u, 0u, 0u);
    p[base + 0 * T] = z;
    p[base + 1 * T] = z;
    p[base + 2 * T] = z;
    p[base + 3 * T] = z;
}

// S: n8 = n/8 threads, each loads 2 int4 of pos and issues 8 fire-and-forget
// RED.MAX into the output buffer (winner-index resolution).
__global__ void scatter_kernel(unsigned int* __restrict__ outw,
                               const int4* __restrict__ p4, int n8) {
    int t = blockIdx.x * blockDim.x + threadIdx.x;
    if (t >= n8) return;
    int4 a = __ldcs(&p4[2 * t + 0]);
    int4 b = __ldcs(&p4[2 * t + 1]);
    unsigned int base = (unsigned int)(t * 8);
    atomicMax(&outw[a.x], base + 1u);
    atomicMax(&outw[a.y], base + 2u);
    atomicMax(&outw[a.z], base + 3u);
    atomicMax(&outw[a.w], base + 4u);
    atomicMax(&outw[b.x], base + 5u);
    atomicMax(&outw[b.y], base + 6u);
    atomicMax(&outw[b.z], base + 7u);
    atomicMax(&outw[b.w], base + 8u);
}

// C: in-place convert. Thread t owns uint4 slots 2t, 2t+1 of the output:
// read winner words (L2-hot from Z/S), gather x, write floats back to the
// SAME addresses. No race: slots are thread-exclusive.
__global__ void convert_kernel(unsigned int* __restrict__ outw,
                               const float* __restrict__ x,
                               int count8) {
    int t = blockIdx.x * blockDim.x + threadIdx.x;
    if (t >= count8) return;

    uint4* __restrict__ sp = reinterpret_cast<uint4*>(outw);

    uint4 w0 = sp[2 * t + 0];
    uint4 w1 = sp[2 * t + 1];

    float4 o0, o1;
    o0.x = w0.x ? __ldg(&x[w0.x - 1u]) : 0.0f;
    o0.y = w0.y ? __ldg(&x[w0.y - 1u]) : 0.0f;
    o0.z = w0.z ? __ldg(&x[w0.z - 1u]) : 0.0f;
    o0.w = w0.w ? __ldg(&x[w0.w - 1u]) : 0.0f;
    o1.x = w1.x ? __ldg(&x[w1.x - 1u]) : 0.0f;
    o1.y = w1.y ? __ldg(&x[w1.y - 1u]) : 0.0f;
    o1.z = w1.z ? __ldg(&x[w1.z - 1u]) : 0.0f;
    o1.w = w1.w ? __ldg(&x[w1.w - 1u]) : 0.0f;

    float4* __restrict__ op = reinterpret_cast<float4*>(outw);
    op[2 * t + 0] = o0;
    op[2 * t + 1] = o1;
}

extern "C" void kernel_launch(void* const* d_in, const int* in_sizes, int n_in,
                              void* d_out, int out_size) {
    const float* x = reinterpret_cast<const float*>(d_in[0]);
    const int* pos = reinterpret_cast<const int*>(d_in[1]);
    unsigned int* outw = reinterpret_cast<unsigned int*>(d_out);

    int n = in_sizes[0];             // 6,422,528 (divisible by 8)
    int n8 = n / 8;                  // 802,816
    int count4 = out_size / 4;       // 6,422,528 uint4 slots
    int count8 = out_size / 8;       // 3,211,264

    const int T = 256;
    const int ZG = count4 / (4 * T); // exact: count4 = 6272*1024
    const int SG = (n8 + T - 1) / T;
    const int CG = (count8 + T - 1) / T;

    // Z: zero the output (it doubles as the winner-index array) + L2-heat.
    zero_out_kernel<<<ZG, T>>>(outw);

    // S: deterministic last-index-wins via 32-bit atomicMax into out.
    scatter_kernel<<<SG, T>>>(outw, reinterpret_cast<const int4*>(pos), n8);

    // C: in-place winner-index -> value conversion.
    convert_kernel<<<CG, T>>>(outw, x, count8);
}

// round 14
// speedup vs baseline: 1.0450x; 1.0436x over previous
#include <cuda_runtime.h>
#include <cstdint>

// Max-unpool scatter, deterministic last-index-wins (matches reference).
//
// Round-14: R5 (champion, 134.8us) byte-exact, ONE change — scatter reads
// pos with __ldg instead of __ldcs. pos is re-read on every graph replay,
// so streaming (evict-first) it was forcing a 26MB DRAM re-read inside the
// latency-critical atomic phase each call. Default caching keeps it
// (mostly) L2-resident across replays.
//   Z: 4 consecutive uint4/thread (R5's exact champion form)
//   S: atomicMax(scr[pos[i]], i+1), 8 atomics/thread, pos via __ldg
//   C: linear 8/thread; scratch __ldcs, x __ldg, out __stcs (R5 exact)

#define N_OUT_CONST 25690112  // 32*112*112*64

__device__ unsigned int g_winner[N_OUT_CONST];

// R5's exact zero form: count16 threads, each writes 4 consecutive uint4.
__global__ void zero_scratch_kernel(int count16) {
    int t = blockIdx.x * blockDim.x + threadIdx.x;
    if (t < count16) {
        uint4* p = reinterpret_cast<uint4*>(g_winner) + 4 * t;
        uint4 z = make_uint4(0u, 0u, 0u, 0u);
        p[0] = z; p[1] = z; p[2] = z; p[3] = z;
    }
}

// n8 = n/8 threads, each loads 2 int4 of pos and issues 8 fire-and-forget
// RED.MAX.
__global__ void scatter_kernel(const int4* __restrict__ p4, int n8) {
    int t = blockIdx.x * blockDim.x + threadIdx.x;
    if (t >= n8) return;
    int4 a = __ldg(&p4[2 * t + 0]);
    int4 b = __ldg(&p4[2 * t + 1]);
    unsigned int base = (unsigned int)(t * 8);
    atomicMax(&g_winner[a.x], base + 1u);
    atomicMax(&g_winner[a.y], base + 2u);
    atomicMax(&g_winner[a.z], base + 3u);
    atomicMax(&g_winner[a.w], base + 4u);
    atomicMax(&g_winner[b.x], base + 5u);
    atomicMax(&g_winner[b.y], base + 6u);
    atomicMax(&g_winner[b.z], base + 7u);
    atomicMax(&g_winner[b.w], base + 8u);
}

// Linear form: thread t consumes uint4 slots 2t, 2t+1, 8 gathers batched,
// 2 float4 streaming stores.
__global__ void compact_kernel(float* __restrict__ out,
                               const float* __restrict__ x,
                               int count8) {
    int t = blockIdx.x * blockDim.x + threadIdx.x;
    if (t >= count8) return;

    const uint4* __restrict__ sp = reinterpret_cast<const uint4*>(g_winner);
    float4* __restrict__ op = reinterpret_cast<float4*>(out);

    uint4 w0 = __ldcs(&sp[2 * t + 0]);
    uint4 w1 = __ldcs(&sp[2 * t + 1]);

    float4 o0, o1;
    o0.x = w0.x ? __ldg(&x[w0.x - 1u]) : 0.0f;
    o0.y = w0.y ? __ldg(&x[w0.y - 1u]) : 0.0f;
    o0.z = w0.z ? __ldg(&x[w0.z - 1u]) : 0.0f;
    o0.w = w0.w ? __ldg(&x[w0.w - 1u]) : 0.0f;
    o1.x = w1.x ? __ldg(&x[w1.x - 1u]) : 0.0f;
    o1.y = w1.y ? __ldg(&x[w1.y - 1u]) : 0.0f;
    o1.z = w1.z ? __ldg(&x[w1.z - 1u]) : 0.0f;
    o1.w = w1.w ? __ldg(&x[w1.w - 1u]) : 0.0f;

    __stcs(&op[2 * t + 0], o0);
    __stcs(&op[2 * t + 1], o1);
}

extern "C" void kernel_launch(void* const* d_in, const int* in_sizes, int n_in,
                              void* d_out, int out_size) {
    const float* x = reinterpret_cast<const float*>(d_in[0]);
    const int* pos = reinterpret_cast<const int*>(d_in[1]);
    float* out     = reinterpret_cast<float*>(d_out);

    int n = in_sizes[0];             // 6,422,528 (divisible by 8)
    int n8 = n / 8;                  // 802,816
    int count16 = out_size / 16;     // 1,605,632
    int count8  = out_size / 8;      // 3,211,264

    const int T = 256;

    // Z: zero the winner scratch (heats it in L2 right before the atomics).
    zero_scratch_kernel<<<(count16 + T - 1) / T, T>>>(count16);

    // S: deterministic last-index-wins via 32-bit atomicMax, 8/thread.
    scatter_kernel<<<(n8 + T - 1) / T, T>>>(
        reinterpret_cast<const int4*>(pos), n8);

    // C: gather winners' values, zero-fill empties, stream out.
    compact_kernel<<<(count8 + T - 1) / T, T>>>(out, x, count8);
}